// round 16
// baseline (speedup 1.0000x reference)
#include <cuda_runtime.h>
#include <cuda_fp16.h>
#include <math.h>
#include <stdint.h>

#define BQ  8
#define TT  2048
#define CC  1024
#define HH  16
#define NN  64
#define FFND 3584
#define BT  (BQ*TT)
#define EPSV 1e-5f
#define CCSQ ((size_t)CC * CC)
#define WKV_L  128
#define WKV_NC (TT / WKV_L)             // 16 chunks

// ------------------------------------------------------------------
// Scratch (device globals; no dynamic allocation allowed)
// ------------------------------------------------------------------
__device__ __align__(256) float  g_bufs[8][(size_t)BT * CC];
__device__ __align__(256) __half g_h[4][(size_t)BT * CC];
__device__ __align__(256) __half g_fh[(size_t)BT * FFND];
__device__ __align__(256) __half g_wh[6 * CCSQ + 2 * (size_t)FFND * CC];

// ==================================================================
// PTX helpers
// ==================================================================
__device__ __forceinline__ uint32_t smem_u32(const void* p) {
    uint32_t a;
    asm("{ .reg .u64 t; cvta.to.shared.u64 t, %1; cvt.u32.u64 %0, t; }" : "=r"(a) : "l"(p));
    return a;
}
__device__ __forceinline__ void cp16(uint32_t dst, const void* src) {
    asm volatile("cp.async.cg.shared.global [%0], [%1], 16;" :: "r"(dst), "l"(src));
}
#define CP_COMMIT() asm volatile("cp.async.commit_group;" ::: "memory")
#define CP_WAIT(n)  asm volatile("cp.async.wait_group %0;" :: "n"(n) : "memory")

__device__ __forceinline__ void ldsm4(uint32_t& r0, uint32_t& r1, uint32_t& r2,
                                      uint32_t& r3, uint32_t addr) {
    asm volatile("ldmatrix.sync.aligned.m8n8.x4.shared.b16 {%0,%1,%2,%3}, [%4];"
                 : "=r"(r0), "=r"(r1), "=r"(r2), "=r"(r3) : "r"(addr));
}
__device__ __forceinline__ void mma_f16(float* c, const uint32_t* a, const uint32_t* b) {
    asm volatile("mma.sync.aligned.m16n8k16.row.col.f32.f16.f16.f32 "
                 "{%0,%1,%2,%3}, {%4,%5,%6,%7}, {%8,%9}, {%0,%1,%2,%3};"
                 : "+f"(c[0]), "+f"(c[1]), "+f"(c[2]), "+f"(c[3])
                 : "r"(a[0]), "r"(a[1]), "r"(a[2]), "r"(a[3]), "r"(b[0]), "r"(b[1]));
}
__device__ __forceinline__ uint32_t pack2(float a, float b) {
    __half2 h = __floats2half2_rn(a, b);
    return *reinterpret_cast<uint32_t*>(&h);
}

// padded group offset: 16-float groups padded to 20 floats
__device__ __forceinline__ uint32_t padoff(int off4) {
    return (uint32_t)((off4 >> 4) * 20 + (off4 & 15));
}

// ==================================================================
// fp16 mma.sync GEMM core: 128x128 CTA tile; 4 warps; 2 CTAs/SM.
// ==================================================================
#define GM_NT     128
#define GM_SLOTSZ 32768
#define GM_SMEM   (3 * GM_SLOTSZ)

__device__ __forceinline__ void load_stage_h(uint32_t sa, const char* pa, const char* pb,
                                             uint32_t sw0, size_t rstride)
{
    uint32_t s = sa + sw0;
    #pragma unroll
    for (int i = 0; i < 8; i++) {
        cp16(s, pa);
        cp16(s + 16384, pb);
        pa += rstride; pb += rstride; s += 2048;
    }
}

__device__ __forceinline__ void gemm_core(
    const __half* Ab, const __half* Bb, int K,
    uint32_t sb, int tid, int lane, int wm, int wn,
    float acc[4][8][4])
{
    int S = K / 64;
    int l16 = lane & 15;
    int chb = (lane >> 4) * 16;

    int r0 = tid >> 3, seg = tid & 7;
    const char* gA = (const char*)(Ab + (size_t)r0 * K + seg * 8);
    const char* gB = (const char*)(Bb + (size_t)r0 * K + seg * 8);
    size_t rstride = (size_t)K * 32;
    uint32_t sw0 = (uint32_t)(r0 * 128 + ((seg * 16) ^ ((r0 & 7) << 4)));

    uint32_t PA[4], PB[4];
    #pragma unroll
    for (int f = 0; f < 4; f++) {
        int rowa = wm * 64 + f * 16 + l16;
        PA[f] = (uint32_t)(rowa * 128 + (chb ^ ((rowa & 7) << 4)));
        int rowb = wn * 64 + f * 16 + l16;
        PB[f] = (uint32_t)(rowb * 128 + (chb ^ ((rowb & 7) << 4)));
    }

    load_stage_h(sb + 0 * GM_SLOTSZ, gA, gB, sw0, rstride);
    CP_COMMIT();
    load_stage_h(sb + 1 * GM_SLOTSZ, gA + 128, gB + 128, sw0, rstride);
    CP_COMMIT();

    for (int s = 0; s < S; s++) {
        CP_WAIT(1);
        __syncthreads();
        if (s + 2 < S)
            load_stage_h(sb + (uint32_t)((s + 2) % 3) * GM_SLOTSZ,
                         gA + (size_t)(s + 2) * 128, gB + (size_t)(s + 2) * 128,
                         sw0, rstride);
        CP_COMMIT();

        uint32_t saA = sb + (uint32_t)(s % 3) * GM_SLOTSZ;
        uint32_t saB = saA + 16384;

        #pragma unroll
        for (int ks = 0; ks < 4; ks++) {
            uint32_t xo = (uint32_t)(ks << 5);
            uint32_t a[4][4], b[8][2];
            #pragma unroll
            for (int mf = 0; mf < 4; mf++)
                ldsm4(a[mf][0], a[mf][1], a[mf][2], a[mf][3], saA + (PA[mf] ^ xo));
            #pragma unroll
            for (int p = 0; p < 4; p++) {
                uint32_t r0_, r1_, r2_, r3_;
                ldsm4(r0_, r1_, r2_, r3_, saB + (PB[p] ^ xo));
                b[2 * p][0] = r0_; b[2 * p][1] = r2_;
                b[2 * p + 1][0] = r1_; b[2 * p + 1][1] = r3_;
            }
            #pragma unroll
            for (int mf = 0; mf < 4; mf++)
                #pragma unroll
                for (int nf = 0; nf < 8; nf++)
                    mma_f16(acc[mf][nf], a[mf], b[nf]);
        }
    }
}

// ------------------------------------------------------------------
// Generic GEMM. EPI: 0=none 1=silu 2=relu^2 3=sigmoid 4=res+gate*acc
// ------------------------------------------------------------------
template<int EPI, bool HOUT>
__global__ void __launch_bounds__(GM_NT, 2) gemm_h(
    const __half* __restrict__ A, const __half* __restrict__ B,
    const float* __restrict__ res, const float* __restrict__ gate,
    void* __restrict__ Cout, int M, int N, int K)
{
    extern __shared__ char smem[];
    uint32_t sb = smem_u32(smem);
    int tid = threadIdx.x;
    int lane = tid & 31, warp = tid >> 5;
    int wm = warp >> 1, wn = warp & 1;
    int bm = blockIdx.y * 128;
    int bn = blockIdx.x * 128;

    float acc[4][8][4];
    #pragma unroll
    for (int i = 0; i < 4; i++)
        #pragma unroll
        for (int j = 0; j < 8; j++)
            #pragma unroll
            for (int l = 0; l < 4; l++) acc[i][j][l] = 0.f;

    gemm_core(A + (size_t)bm * K, B + (size_t)bn * K, K, sb, tid, lane, wm, wn, acc);

    int r0r = bm + wm * 64 + (lane >> 2);
    int cbase = bn + wn * 64 + (lane & 3) * 2;
    #pragma unroll
    for (int mf = 0; mf < 4; mf++) {
        #pragma unroll
        for (int half = 0; half < 2; half++) {
            int m = r0r + mf * 16 + half * 8;
            size_t rowoff = (size_t)m * N + cbase;
            #pragma unroll
            for (int nf = 0; nf < 8; nf++) {
                float vx = acc[mf][nf][half * 2 + 0];
                float vy = acc[mf][nf][half * 2 + 1];
                size_t o = rowoff + nf * 8;
                if (EPI == 4) {
                    float2 rv = *(const float2*)(res + o);
                    float2 gv = *(const float2*)(gate + o);
                    vx = fmaf(gv.x, vx, rv.x); vy = fmaf(gv.y, vy, rv.y);
                } else if (res) {
                    float2 rv = *(const float2*)(res + o);
                    vx += rv.x; vy += rv.y;
                }
                if (EPI == 1) {
                    vx = vx / (1.f + expf(-vx)); vy = vy / (1.f + expf(-vy));
                } else if (EPI == 2) {
                    vx = fmaxf(vx, 0.f); vx *= vx;
                    vy = fmaxf(vy, 0.f); vy *= vy;
                } else if (EPI == 3) {
                    vx = 1.f / (1.f + expf(-vx)); vy = 1.f / (1.f + expf(-vy));
                }
                if (HOUT) {
                    *(uint32_t*)((__half*)Cout + o) = pack2(vx, vy);
                } else {
                    *(float2*)((float*)Cout + o) = make_float2(vx, vy);
                }
            }
        }
    }
}

// ------------------------------------------------------------------
// Batched 4-way projection GEMM (r,k,v fp32; g silu fp16).
// ------------------------------------------------------------------
struct Proj4 {
    const __half* A[4];
    const __half* W[4];
    float* Cf[3];
    __half* Ch;
};

__global__ void __launch_bounds__(GM_NT, 2) gemm_proj4(Proj4 p)
{
    extern __shared__ char smem[];
    uint32_t sb = smem_u32(smem);
    int tid = threadIdx.x;
    int lane = tid & 31, warp = tid >> 5;
    int wm = warp >> 1, wn = warp & 1;
    int bm = blockIdx.y * 128;
    int bn = blockIdx.x * 128;
    int z = blockIdx.z;

    float acc[4][8][4];
    #pragma unroll
    for (int i = 0; i < 4; i++)
        #pragma unroll
        for (int j = 0; j < 8; j++)
            #pragma unroll
            for (int l = 0; l < 4; l++) acc[i][j][l] = 0.f;

    gemm_core(p.A[z] + (size_t)bm * CC, p.W[z] + (size_t)bn * CC, CC,
              sb, tid, lane, wm, wn, acc);

    int r0r = bm + wm * 64 + (lane >> 2);
    int cbase = bn + wn * 64 + (lane & 3) * 2;
    bool is_g = (z == 3);
    #pragma unroll
    for (int mf = 0; mf < 4; mf++) {
        #pragma unroll
        for (int half = 0; half < 2; half++) {
            int m = r0r + mf * 16 + half * 8;
            size_t rowoff = (size_t)m * CC + cbase;
            #pragma unroll
            for (int nf = 0; nf < 8; nf++) {
                float vx = acc[mf][nf][half * 2 + 0];
                float vy = acc[mf][nf][half * 2 + 1];
                size_t o = rowoff + nf * 8;
                if (is_g) {
                    vx = vx / (1.f + expf(-vx));
                    vy = vy / (1.f + expf(-vy));
                    *(uint32_t*)(p.Ch + o) = pack2(vx, vy);
                } else {
                    *(float2*)(p.Cf[z] + o) = make_float2(vx, vy);
                }
            }
        }
    }
}

// ------------------------------------------------------------------
// Fused FFN-input GEMMs: blockIdx.x < 28 -> relu^2 (N=3584, fp16 out);
// else sigmoid (N=1024, fp32 out). Same K=CC, same M rows.
// ------------------------------------------------------------------
__global__ void __launch_bounds__(GM_NT, 2) gemm_ffn2(
    const __half* __restrict__ Ak, const __half* __restrict__ Wk,
    __half* __restrict__ Ck,
    const __half* __restrict__ Ar, const __half* __restrict__ Wr,
    float* __restrict__ Cr)
{
    extern __shared__ char smem[];
    uint32_t sb = smem_u32(smem);
    int tid = threadIdx.x;
    int lane = tid & 31, warp = tid >> 5;
    int wm = warp >> 1, wn = warp & 1;
    int bm = blockIdx.y * 128;
    bool is_k = (blockIdx.x < FFND / 128);
    int bn = (is_k ? blockIdx.x : (blockIdx.x - FFND / 128)) * 128;

    const __half* A = is_k ? Ak : Ar;
    const __half* W = is_k ? Wk : Wr;

    float acc[4][8][4];
    #pragma unroll
    for (int i = 0; i < 4; i++)
        #pragma unroll
        for (int j = 0; j < 8; j++)
            #pragma unroll
            for (int l = 0; l < 4; l++) acc[i][j][l] = 0.f;

    gemm_core(A + (size_t)bm * CC, W + (size_t)bn * CC, CC, sb, tid, lane, wm, wn, acc);

    int r0r = bm + wm * 64 + (lane >> 2);
    int cbase = bn + wn * 64 + (lane & 3) * 2;
    #pragma unroll
    for (int mf = 0; mf < 4; mf++) {
        #pragma unroll
        for (int half = 0; half < 2; half++) {
            int m = r0r + mf * 16 + half * 8;
            #pragma unroll
            for (int nf = 0; nf < 8; nf++) {
                float vx = acc[mf][nf][half * 2 + 0];
                float vy = acc[mf][nf][half * 2 + 1];
                if (is_k) {
                    vx = fmaxf(vx, 0.f); vx *= vx;
                    vy = fmaxf(vy, 0.f); vy *= vy;
                    size_t o = (size_t)m * FFND + cbase + nf * 8;
                    *(uint32_t*)(Ck + o) = pack2(vx, vy);
                } else {
                    vx = 1.f / (1.f + expf(-vx));
                    vy = 1.f / (1.f + expf(-vy));
                    size_t o = (size_t)m * CC + cbase + nf * 8;
                    *(float2*)(Cr + o) = make_float2(vx, vy);
                }
            }
        }
    }
}

// ------------------------------------------------------------------
// wkv sweep 1: chunk-local END-STATE only. 4 steps per barrier.
// slot = 4 x 144 floats (k padded 80 | v 64); ring of 3.
// ------------------------------------------------------------------
__global__ void __launch_bounds__(256) wkv_s1_kernel(
    const float* __restrict__ k, const float* __restrict__ v,
    const float* __restrict__ decay, float* __restrict__ Schunk)
{
    int blk = blockIdx.x;
    int bh = blk >> 4, c = blk & (WKV_NC - 1);
    int b = bh / HH, h = bh % HH;
    int tid = threadIdx.x;
    int j = tid >> 2, ig = tid & 3;

    float S[16], ww[16];
    #pragma unroll
    for (int m = 0; m < 16; m++) {
        S[m] = 0.f;
        ww[m] = expf(-expf(decay[h * NN + ig * 16 + m]));
    }

    __shared__ __align__(16) float buf[3 * 576];
    uint32_t sbuf = smem_u32(buf);

    size_t base = ((size_t)b * TT + (size_t)c * WKV_L) * CC + h * NN;

    const float* srcs[2] = { k, v };
    int lstep = tid >> 5;                 // 0..3 for tid<128
    int lrem = tid & 31;
    int part = lrem >> 4;                 // 0=k, 1=v
    int off4 = (lrem & 15) * 4;
    uint32_t doff = (part == 0) ? padoff(off4) : (80u + (uint32_t)off4);

    #pragma unroll
    for (int pi = 0; pi < 2; pi++) {
        if (tid < 128)
            cp16(sbuf + (uint32_t)(pi * 576 + lstep * 144 + doff) * 4,
                 srcs[part] + base + (size_t)(4 * pi + lstep) * CC + off4);
        CP_COMMIT();
    }

    const int NG = WKV_L / 4;             // 32 groups
    for (int pi = 0; pi < NG; pi++) {
        CP_WAIT(1);
        __syncthreads();
        if (pi + 2 < NG && tid < 128)
            cp16(sbuf + (uint32_t)(((pi + 2) % 3) * 576 + lstep * 144 + doff) * 4,
                 srcs[part] + base + (size_t)(4 * (pi + 2) + lstep) * CC + off4);
        CP_COMMIT();

        const float* slot = buf + (pi % 3) * 576;
        #pragma unroll
        for (int s = 0; s < 4; s++) {
            const float* sl = slot + s * 144;
            float4 K4[4];
            #pragma unroll
            for (int q = 0; q < 4; q++)
                K4[q] = *(const float4*)(sl + ig * 20 + q * 4);
            float vj = sl[80 + j];
            const float* kk = (const float*)K4;
            #pragma unroll
            for (int m = 0; m < 16; m++)
                S[m] = fmaf(ww[m], S[m], kk[m] * vj);
        }
    }

    size_t sbase = (size_t)blk * 4096 + (size_t)j * 64 + ig * 16;
    #pragma unroll
    for (int q = 0; q < 4; q++)
        *(float4*)(Schunk + sbase + q * 4) =
            make_float4(S[q * 4 + 0], S[q * 4 + 1], S[q * 4 + 2], S[q * 4 + 3]);
}

// ------------------------------------------------------------------
// wkv scan: in-place exclusive scan over chunks.
// ------------------------------------------------------------------
__global__ void __launch_bounds__(256) wkv_scan_kernel(
    const float* __restrict__ decay, float* __restrict__ Schunk)
{
    int idx = blockIdx.x * 256 + threadIdx.x;
    int bh = idx >> 12;
    int e = idx & 4095;
    int h = bh % HH;
    int i = e & 63;
    float ewL = expf(-expf(decay[h * NN + i]) * (float)WKV_L);

    size_t base = (size_t)bh * WKV_NC * 4096 + e;
    float sinit = 0.f;
    #pragma unroll
    for (int c = 0; c < WKV_NC; c++) {
        size_t o = base + (size_t)c * 4096;
        float cur = Schunk[o];
        Schunk[o] = sinit;
        sinit = fmaf(ewL, sinit, cur);
    }
}

// ------------------------------------------------------------------
// wkv sweep 2: full recurrence with init state. 4 steps per barrier.
// slot = 4 x 224 floats (r pad 80 | k pad 80 | v 64); ring of 3.
// ------------------------------------------------------------------
__global__ void __launch_bounds__(256) wkv_s2_kernel(
    const float* __restrict__ r, const float* __restrict__ k,
    const float* __restrict__ v,
    const float* __restrict__ decay, const float* __restrict__ faaaa,
    const float* __restrict__ Schunk, float* __restrict__ out)
{
    int blk = blockIdx.x;
    int bh = blk >> 4, c = blk & (WKV_NC - 1);
    int b = bh / HH, h = bh % HH;
    int tid = threadIdx.x;
    int j = tid >> 2, ig = tid & 3;

    float S[16], uu[16], ww[16];
    size_t sbase = (size_t)blk * 4096 + (size_t)j * 64 + ig * 16;
    #pragma unroll
    for (int q = 0; q < 4; q++) {
        float4 sv = *(const float4*)(Schunk + sbase + q * 4);
        S[q * 4 + 0] = sv.x; S[q * 4 + 1] = sv.y;
        S[q * 4 + 2] = sv.z; S[q * 4 + 3] = sv.w;
    }
    #pragma unroll
    for (int m = 0; m < 16; m++) {
        int i = ig * 16 + m;
        uu[m] = faaaa[h * NN + i];
        ww[m] = expf(-expf(decay[h * NN + i]));
    }

    __shared__ __align__(16) float buf[3 * 896];
    uint32_t sbuf = smem_u32(buf);

    size_t base = ((size_t)b * TT + (size_t)c * WKV_L) * CC + h * NN;

    const float* srcs[3] = { r, k, v };
    int lstep = tid / 48;                 // 0..3 for tid<192
    int lrem = tid % 48;
    int part = lrem >> 4;
    int off4 = (lrem & 15) * 4;
    uint32_t doff = (part < 2) ? ((uint32_t)part * 80 + padoff(off4))
                               : (160u + (uint32_t)off4);

    #pragma unroll
    for (int pi = 0; pi < 2; pi++) {
        if (tid < 192)
            cp16(sbuf + (uint32_t)(pi * 896 + lstep * 224 + doff) * 4,
                 srcs[part] + base + (size_t)(4 * pi + lstep) * CC + off4);
        CP_COMMIT();
    }

    const int NG = WKV_L / 4;
    for (int pi = 0; pi < NG; pi++) {
        CP_WAIT(1);
        __syncthreads();
        if (pi + 2 < NG && tid < 192)
            cp16(sbuf + (uint32_t)(((pi + 2) % 3) * 896 + lstep * 224 + doff) * 4,
                 srcs[part] + base + (size_t)(4 * (pi + 2) + lstep) * CC + off4);
        CP_COMMIT();

        const float* slot = buf + (pi % 3) * 896;
        #pragma unroll
        for (int s = 0; s < 4; s++) {
            const float* sl = slot + s * 224;
            float4 R4[4], K4[4];
            #pragma unroll
            for (int q = 0; q < 4; q++) {
                R4[q] = *(const float4*)(sl + ig * 20 + q * 4);
                K4[q] = *(const float4*)(sl + 80 + ig * 20 + q * 4);
            }
            float vj = sl[160 + j];
            const float* rr = (const float*)R4;
            const float* kk = (const float*)K4;
            float y = 0.f;
            #pragma unroll
            for (int m = 0; m < 16; m++) {
                float a = kk[m] * vj;
                y = fmaf(rr[m], fmaf(uu[m], a, S[m]), y);
                S[m] = fmaf(ww[m], S[m], a);
            }
            y += __shfl_xor_sync(0xffffffffu, y, 1);
            y += __shfl_xor_sync(0xffffffffu, y, 2);
            if (ig == 0) out[base + (size_t)(4 * pi + s) * CC + j] = y;
        }
    }
}

// ------------------------------------------------------------------
// Batched fp32 -> fp16 conversion for all 8 weights (one launch).
// ------------------------------------------------------------------
struct Cvt8 {
    const float4* src[8];
    uint2* dst[8];
    int n4[8];
};

__global__ void __launch_bounds__(256) cvt8_kernel(Cvt8 c)
{
    int z = blockIdx.z;
    int i = blockIdx.x * 256 + threadIdx.x;
    if (i < c.n4[z]) {
        float4 v = c.src[z][i];
        c.dst[z][i] = make_uint2(pack2(v.x, v.y), pack2(v.z, v.w));
    }
}

// ------------------------------------------------------------------
// Block-wide reduction of (sum, sumsq) across 256 threads
// ------------------------------------------------------------------
__device__ __forceinline__ void block_reduce_2(float& s, float& s2) {
    __shared__ float sh[16];
    #pragma unroll
    for (int o = 16; o > 0; o >>= 1) {
        s  += __shfl_xor_sync(0xffffffffu, s,  o);
        s2 += __shfl_xor_sync(0xffffffffu, s2, o);
    }
    int wid = threadIdx.x >> 5;
    if ((threadIdx.x & 31) == 0) { sh[wid] = s; sh[8 + wid] = s2; }
    __syncthreads();
    float a = 0.f, b = 0.f;
    #pragma unroll
    for (int i = 0; i < 8; i++) { a += sh[i]; b += sh[8 + i]; }
    s = a; s2 = b;
    __syncthreads();
}

__device__ __forceinline__ float4 ln_apply(float4 v, float mu, float rstd,
                                           const float4 w, const float4 b) {
    return make_float4((v.x - mu) * rstd * w.x + b.x,
                       (v.y - mu) * rstd * w.y + b.y,
                       (v.z - mu) * rstd * w.z + b.z,
                       (v.w - mu) * rstd * w.w + b.w);
}
__device__ __forceinline__ void sum2_f4(float4 v, float& s, float& s2) {
    s += v.x + v.y + v.z + v.w;
    s2 += v.x * v.x + v.y * v.y + v.z * v.z + v.w * v.w;
}

// ------------------------------------------------------------------
// Fused ln0+ln1+mix4 (one block per row).
// ------------------------------------------------------------------
__global__ void __launch_bounds__(256) l01m4_kernel(
    const float* __restrict__ x,
    const float* __restrict__ w0, const float* __restrict__ b0,
    const float* __restrict__ w1, const float* __restrict__ b1,
    const float* __restrict__ tmk, const float* __restrict__ tmv,
    const float* __restrict__ tmr, const float* __restrict__ tmg,
    float* __restrict__ x0,
    uint2* __restrict__ xk, uint2* __restrict__ xv,
    uint2* __restrict__ xr, uint2* __restrict__ xg)
{
    int row = blockIdx.x;
    int tseq = row & (TT - 1);
    int c = threadIdx.x * 4;
    size_t base = (size_t)row * CC;
    float4 W0 = *(const float4*)(w0 + c), B0v = *(const float4*)(b0 + c);
    float4 W1 = *(const float4*)(w1 + c), B1v = *(const float4*)(b1 + c);

    float4 ct = *(const float4*)(x + base + c);
    float s = 0.f, s2 = 0.f;
    sum2_f4(ct, s, s2);
    block_reduce_2(s, s2);
    float mu = s * (1.f / CC);
    float rstd = rsqrtf(s2 * (1.f / CC) - mu * mu + EPSV);
    float4 t0 = ln_apply(ct, mu, rstd, W0, B0v);
    *(float4*)(x0 + base + c) = t0;
    s = 0.f; s2 = 0.f;
    sum2_f4(t0, s, s2);
    block_reduce_2(s, s2);
    mu = s * (1.f / CC);
    rstd = rsqrtf(s2 * (1.f / CC) - mu * mu + EPSV);
    float4 nt = ln_apply(t0, mu, rstd, W1, B1v);

    float4 np = make_float4(0.f, 0.f, 0.f, 0.f);
    if (tseq != 0) {
        float4 cp = *(const float4*)(x + base - CC + c);
        s = 0.f; s2 = 0.f;
        sum2_f4(cp, s, s2);
        block_reduce_2(s, s2);
        mu = s * (1.f / CC);
        rstd = rsqrtf(s2 * (1.f / CC) - mu * mu + EPSV);
        float4 p0 = ln_apply(cp, mu, rstd, W0, B0v);
        s = 0.f; s2 = 0.f;
        sum2_f4(p0, s, s2);
        block_reduce_2(s, s2);
        mu = s * (1.f / CC);
        rstd = rsqrtf(s2 * (1.f / CC) - mu * mu + EPSV);
        np = ln_apply(p0, mu, rstd, W1, B1v);
    }

    float dx = nt.x - np.x, dy = nt.y - np.y, dz = nt.z - np.z, dw = nt.w - np.w;
    int o = (int)(base / 4) + threadIdx.x;
    float4 m;
    m = *(const float4*)(tmk + c);
    xk[o] = make_uint2(pack2(fmaf(dx, m.x, np.x), fmaf(dy, m.y, np.y)),
                       pack2(fmaf(dz, m.z, np.z), fmaf(dw, m.w, np.w)));
    m = *(const float4*)(tmv + c);
    xv[o] = make_uint2(pack2(fmaf(dx, m.x, np.x), fmaf(dy, m.y, np.y)),
                       pack2(fmaf(dz, m.z, np.z), fmaf(dw, m.w, np.w)));
    m = *(const float4*)(tmr + c);
    xr[o] = make_uint2(pack2(fmaf(dx, m.x, np.x), fmaf(dy, m.y, np.y)),
                       pack2(fmaf(dz, m.z, np.z), fmaf(dw, m.w, np.w)));
    m = *(const float4*)(tmg + c);
    xg[o] = make_uint2(pack2(fmaf(dx, m.x, np.x), fmaf(dy, m.y, np.y)),
                       pack2(fmaf(dz, m.z, np.z), fmaf(dw, m.w, np.w)));
}

// ------------------------------------------------------------------
// Fused ln2+mix2 (one block per row).
// ------------------------------------------------------------------
__global__ void __launch_bounds__(256) lnm2_kernel(
    const float* __restrict__ in,
    const float* __restrict__ w, const float* __restrict__ b,
    const float* __restrict__ tmk, const float* __restrict__ tmr,
    uint2* __restrict__ xk, uint2* __restrict__ xr)
{
    int row = blockIdx.x;
    int tseq = row & (TT - 1);
    int c = threadIdx.x * 4;
    size_t base = (size_t)row * CC;
    float4 W = *(const float4*)(w + c), Bv = *(const float4*)(b + c);

    float4 ct = *(const float4*)(in + base + c);
    float s = 0.f, s2 = 0.f;
    sum2_f4(ct, s, s2);
    block_reduce_2(s, s2);
    float mu = s * (1.f / CC);
    float rstd = rsqrtf(s2 * (1.f / CC) - mu * mu + EPSV);
    float4 nt = ln_apply(ct, mu, rstd, W, Bv);

    float4 np = make_float4(0.f, 0.f, 0.f, 0.f);
    if (tseq != 0) {
        float4 cp = *(const float4*)(in + base - CC + c);
        s = 0.f; s2 = 0.f;
        sum2_f4(cp, s, s2);
        block_reduce_2(s, s2);
        mu = s * (1.f / CC);
        rstd = rsqrtf(s2 * (1.f / CC) - mu * mu + EPSV);
        np = ln_apply(cp, mu, rstd, W, Bv);
    }

    float dx = nt.x - np.x, dy = nt.y - np.y, dz = nt.z - np.z, dw = nt.w - np.w;
    int o = (int)(base / 4) + threadIdx.x;
    float4 m;
    m = *(const float4*)(tmk + c);
    xk[o] = make_uint2(pack2(fmaf(dx, m.x, np.x), fmaf(dy, m.y, np.y)),
                       pack2(fmaf(dz, m.z, np.z), fmaf(dw, m.w, np.w)));
    m = *(const float4*)(tmr + c);
    xr[o] = make_uint2(pack2(fmaf(dx, m.x, np.x), fmaf(dy, m.y, np.y)),
                       pack2(fmaf(dz, m.z, np.z), fmaf(dw, m.w, np.w)));
}

// ------------------------------------------------------------------
// GroupNorm(y/8) * g(fp16)  -> fp16 output (one block per row)
// ------------------------------------------------------------------
__global__ void __launch_bounds__(256) gn_gate_kernel(
    const float* __restrict__ y, const __half* __restrict__ g,
    const float* __restrict__ w, const float* __restrict__ b,
    __half* __restrict__ out)
{
    int row = blockIdx.x;
    size_t base = (size_t)row * CC;
    int gi = threadIdx.x >> 4;
    int sub = threadIdx.x & 15;
    float v[4];
    float s = 0.f, s2 = 0.f;
    #pragma unroll
    for (int l = 0; l < 4; l++) {
        int c = gi * 64 + l * 16 + sub;
        v[l] = y[base + c] * 0.125f;
        s += v[l]; s2 += v[l] * v[l];
    }
    #pragma unroll
    for (int o = 8; o > 0; o >>= 1) {
        s  += __shfl_xor_sync(0xffffffffu, s,  o);
        s2 += __shfl_xor_sync(0xffffffffu, s2, o);
    }
    float mu = s * (1.f / 64);
    float rstd = rsqrtf(s2 * (1.f / 64) - mu * mu + EPSV);
    #pragma unroll
    for (int l = 0; l < 4; l++) {
        int c = gi * 64 + l * 16 + sub;
        float val = ((v[l] - mu) * rstd * w[c] + b[c]) * __half2float(g[base + c]);
        out[base + c] = __float2half(val);
    }
}

// ------------------------------------------------------------------
// Launch
// ------------------------------------------------------------------
extern "C" void kernel_launch(void* const* d_in, const int* in_sizes, int n_in,
                              void* d_out, int out_size)
{
    const float* x        = (const float*)d_in[0];
    const float* ln0_w    = (const float*)d_in[1];
    const float* ln0_b    = (const float*)d_in[2];
    const float* ln1_w    = (const float*)d_in[3];
    const float* ln1_b    = (const float*)d_in[4];
    const float* ln2_w    = (const float*)d_in[5];
    const float* ln2_b    = (const float*)d_in[6];
    const float* att_tmk  = (const float*)d_in[7];
    const float* att_tmv  = (const float*)d_in[8];
    const float* att_tmr  = (const float*)d_in[9];
    const float* att_tmg  = (const float*)d_in[10];
    const float* att_decay= (const float*)d_in[11];
    const float* att_faaaa= (const float*)d_in[12];
    const float* att_Wr   = (const float*)d_in[13];
    const float* att_Wk   = (const float*)d_in[14];
    const float* att_Wv   = (const float*)d_in[15];
    const float* att_Wg   = (const float*)d_in[16];
    const float* att_Wo   = (const float*)d_in[17];
    const float* lnx_w    = (const float*)d_in[18];
    const float* lnx_b    = (const float*)d_in[19];
    const float* ffn_tmk  = (const float*)d_in[20];
    const float* ffn_tmr  = (const float*)d_in[21];
    const float* ffn_Wk   = (const float*)d_in[22];
    const float* ffn_Wr   = (const float*)d_in[23];
    const float* ffn_Wv   = (const float*)d_in[24];

    float* base = nullptr;
    cudaGetSymbolAddress((void**)&base, g_bufs);
    __half* H = nullptr;
    cudaGetSymbolAddress((void**)&H, g_h);
    __half* FH = nullptr;
    cudaGetSymbolAddress((void**)&FH, g_fh);
    __half* WH = nullptr;
    cudaGetSymbolAddress((void**)&WH, g_wh);

    float* B0 = base + 0 * (size_t)BT * CC;
    float* B1 = base + 1 * (size_t)BT * CC;
    float* B2 = base + 2 * (size_t)BT * CC;   // Schunk scratch
    float* B3 = base + 3 * (size_t)BT * CC;
    float* B5 = base + 5 * (size_t)BT * CC;
    float* B6 = base + 6 * (size_t)BT * CC;
    float* B7 = base + 7 * (size_t)BT * CC;
    __half* H0 = H + 0 * (size_t)BT * CC;
    __half* H1 = H + 1 * (size_t)BT * CC;
    __half* H2 = H + 2 * (size_t)BT * CC;
    __half* H3 = H + 3 * (size_t)BT * CC;
    __half* WHr = WH + 0 * CCSQ;
    __half* WHk = WH + 1 * CCSQ;
    __half* WHv = WH + 2 * CCSQ;
    __half* WHg = WH + 3 * CCSQ;
    __half* WHo = WH + 4 * CCSQ;
    __half* WHfr = WH + 5 * CCSQ;
    __half* WHfk = WH + 6 * CCSQ;
    __half* WHfv = WHfk + (size_t)FFND * CC;
    float* out = (float*)d_out;
    float* Schunk = B2;

    cudaFuncSetAttribute(gemm_h<0,false>, cudaFuncAttributeMaxDynamicSharedMemorySize, GM_SMEM);
    cudaFuncSetAttribute(gemm_h<4,false>, cudaFuncAttributeMaxDynamicSharedMemorySize, GM_SMEM);
    cudaFuncSetAttribute(gemm_proj4,      cudaFuncAttributeMaxDynamicSharedMemorySize, GM_SMEM);
    cudaFuncSetAttribute(gemm_ffn2,       cudaFuncAttributeMaxDynamicSharedMemorySize, GM_SMEM);

    dim3 gC(CC / 128, BT / 128);
    dim3 gP(CC / 128, BT / 128, 4);
    dim3 gF2(FFND / 128 + CC / 128, BT / 128);   // fused relu^2 + sigmoid

    // batched weight conversion
    {
        Cvt8 c;
        c.src[0] = (const float4*)att_Wr; c.dst[0] = (uint2*)WHr; c.n4[0] = CCSQ / 4;
        c.src[1] = (const float4*)att_Wk; c.dst[1] = (uint2*)WHk; c.n4[1] = CCSQ / 4;
        c.src[2] = (const float4*)att_Wv; c.dst[2] = (uint2*)WHv; c.n4[2] = CCSQ / 4;
        c.src[3] = (const float4*)att_Wg; c.dst[3] = (uint2*)WHg; c.n4[3] = CCSQ / 4;
        c.src[4] = (const float4*)att_Wo; c.dst[4] = (uint2*)WHo; c.n4[4] = CCSQ / 4;
        c.src[5] = (const float4*)ffn_Wr; c.dst[5] = (uint2*)WHfr; c.n4[5] = CCSQ / 4;
        c.src[6] = (const float4*)ffn_Wk; c.dst[6] = (uint2*)WHfk; c.n4[6] = (int)((size_t)FFND * CC / 4);
        c.src[7] = (const float4*)ffn_Wv; c.dst[7] = (uint2*)WHfv; c.n4[7] = (int)((size_t)FFND * CC / 4);
        dim3 gcv((unsigned)(((size_t)FFND * CC / 4 + 255) / 256), 1, 8);
        cvt8_kernel<<<gcv, 256>>>(c);
    }

    // fused ln0+ln1+mix4
    l01m4_kernel<<<BT, 256>>>(x, ln0_w, ln0_b, ln1_w, ln1_b,
                              att_tmk, att_tmv, att_tmr, att_tmg,
                              B0, (uint2*)H0, (uint2*)H1, (uint2*)H2, (uint2*)H3);
    // batched projections: r->B6, k->B7, v->B1, g(silu,fp16)->FH
    {
        Proj4 p;
        p.A[0] = H2; p.W[0] = WHr; p.Cf[0] = B6;
        p.A[1] = H0; p.W[1] = WHk; p.Cf[1] = B7;
        p.A[2] = H1; p.W[2] = WHv; p.Cf[2] = B1;
        p.A[3] = H3; p.W[3] = WHg; p.Ch = FH;
        gemm_proj4<<<gP, GM_NT, GM_SMEM>>>(p);
    }
    // chunked wkv: state sweep -> scan -> full sweep
    wkv_s1_kernel<<<BQ * HH * WKV_NC, 256>>>(B7, B1, att_decay, Schunk);
    wkv_scan_kernel<<<(BQ * HH * 4096) / 256, 256>>>(att_decay, Schunk);
    wkv_s2_kernel<<<BQ * HH * WKV_NC, 256>>>(B6, B7, B1, att_decay, att_faaaa,
                                             Schunk, B3);
    // groupnorm(y/8) * g -> H0 (fp16)
    gn_gate_kernel<<<BT, 256>>>(B3, FH, lnx_w, lnx_b, H0);
    // x_att = x0 + (gy) @ Wo^T -> B5
    gemm_h<0,false><<<gC, GM_NT, GM_SMEM>>>(H0, WHo, B0, nullptr, B5, BT, CC, CC);
    // fused ln2+mix2: B5 -> H2=xk, H3=xr (fp16)
    lnm2_kernel<<<BT, 256>>>(B5, ln2_w, ln2_b, ffn_tmk, ffn_tmr,
                             (uint2*)H2, (uint2*)H3);
    // fused FFN-input GEMMs: relu^2(H2 Wfk)->FH, sigmoid(H3 Wfr)->B7
    gemm_ffn2<<<gF2, GM_NT, GM_SMEM>>>(H2, WHfk, FH, H3, WHfr, B7);
    // kv GEMM with fused final: out = B5 + B7 * (FH @ Wv^T)
    gemm_h<4,false><<<gC, GM_NT, GM_SMEM>>>(FH, WHfv, B5, B7, out, BT, CC, FFND);
}

// round 17
// speedup vs baseline: 1.5119x; 1.5119x over previous
#include <cuda_runtime.h>
#include <cuda_fp16.h>
#include <math.h>
#include <stdint.h>

#define BQ  8
#define TT  2048
#define CC  1024
#define HH  16
#define NN  64
#define FFND 3584
#define BT  (BQ*TT)
#define EPSV 1e-5f
#define CCSQ ((size_t)CC * CC)
#define WKV_L  128
#define WKV_NC (TT / WKV_L)             // 16 chunks

// ------------------------------------------------------------------
// Scratch (device globals; no dynamic allocation allowed)
// ------------------------------------------------------------------
__device__ __align__(256) float  g_bufs[8][(size_t)BT * CC];
__device__ __align__(256) __half g_h[4][(size_t)BT * CC];
__device__ __align__(256) __half g_fh[(size_t)BT * FFND];
__device__ __align__(256) __half g_wh[6 * CCSQ + 2 * (size_t)FFND * CC];

// ==================================================================
// PTX helpers
// ==================================================================
__device__ __forceinline__ uint32_t smem_u32(const void* p) {
    uint32_t a;
    asm("{ .reg .u64 t; cvta.to.shared.u64 t, %1; cvt.u32.u64 %0, t; }" : "=r"(a) : "l"(p));
    return a;
}
__device__ __forceinline__ void cp16(uint32_t dst, const void* src) {
    asm volatile("cp.async.cg.shared.global [%0], [%1], 16;" :: "r"(dst), "l"(src));
}
#define CP_COMMIT() asm volatile("cp.async.commit_group;" ::: "memory")
#define CP_WAIT(n)  asm volatile("cp.async.wait_group %0;" :: "n"(n) : "memory")

__device__ __forceinline__ void ldsm4(uint32_t& r0, uint32_t& r1, uint32_t& r2,
                                      uint32_t& r3, uint32_t addr) {
    asm volatile("ldmatrix.sync.aligned.m8n8.x4.shared.b16 {%0,%1,%2,%3}, [%4];"
                 : "=r"(r0), "=r"(r1), "=r"(r2), "=r"(r3) : "r"(addr));
}
__device__ __forceinline__ void mma_f16(float* c, const uint32_t* a, const uint32_t* b) {
    asm volatile("mma.sync.aligned.m16n8k16.row.col.f32.f16.f16.f32 "
                 "{%0,%1,%2,%3}, {%4,%5,%6,%7}, {%8,%9}, {%0,%1,%2,%3};"
                 : "+f"(c[0]), "+f"(c[1]), "+f"(c[2]), "+f"(c[3])
                 : "r"(a[0]), "r"(a[1]), "r"(a[2]), "r"(a[3]), "r"(b[0]), "r"(b[1]));
}
__device__ __forceinline__ uint32_t pack2(float a, float b) {
    __half2 h = __floats2half2_rn(a, b);
    return *reinterpret_cast<uint32_t*>(&h);
}

// padded group offset: 16-float groups padded to 20 floats
__device__ __forceinline__ uint32_t padoff(int off4) {
    return (uint32_t)((off4 >> 4) * 20 + (off4 & 15));
}

// ==================================================================
// fp16 mma.sync GEMM core: 128x128 CTA tile; 4 warps; 2 CTAs/SM.
// ==================================================================
#define GM_NT     128
#define GM_SLOTSZ 32768
#define GM_SMEM   (3 * GM_SLOTSZ)

__device__ __forceinline__ void load_stage_h(uint32_t sa, const char* pa, const char* pb,
                                             uint32_t sw0, size_t rstride)
{
    uint32_t s = sa + sw0;
    #pragma unroll
    for (int i = 0; i < 8; i++) {
        cp16(s, pa);
        cp16(s + 16384, pb);
        pa += rstride; pb += rstride; s += 2048;
    }
}

__device__ __forceinline__ void gemm_core(
    const __half* Ab, const __half* Bb, int K,
    uint32_t sb, int tid, int lane, int wm, int wn,
    float acc[4][8][4])
{
    int S = K / 64;
    int l16 = lane & 15;
    int chb = (lane >> 4) * 16;

    int r0 = tid >> 3, seg = tid & 7;
    const char* gA = (const char*)(Ab + (size_t)r0 * K + seg * 8);
    const char* gB = (const char*)(Bb + (size_t)r0 * K + seg * 8);
    size_t rstride = (size_t)K * 32;
    uint32_t sw0 = (uint32_t)(r0 * 128 + ((seg * 16) ^ ((r0 & 7) << 4)));

    uint32_t PA[4], PB[4];
    #pragma unroll
    for (int f = 0; f < 4; f++) {
        int rowa = wm * 64 + f * 16 + l16;
        PA[f] = (uint32_t)(rowa * 128 + (chb ^ ((rowa & 7) << 4)));
        int rowb = wn * 64 + f * 16 + l16;
        PB[f] = (uint32_t)(rowb * 128 + (chb ^ ((rowb & 7) << 4)));
    }

    load_stage_h(sb + 0 * GM_SLOTSZ, gA, gB, sw0, rstride);
    CP_COMMIT();
    load_stage_h(sb + 1 * GM_SLOTSZ, gA + 128, gB + 128, sw0, rstride);
    CP_COMMIT();

    for (int s = 0; s < S; s++) {
        CP_WAIT(1);
        __syncthreads();
        if (s + 2 < S)
            load_stage_h(sb + (uint32_t)((s + 2) % 3) * GM_SLOTSZ,
                         gA + (size_t)(s + 2) * 128, gB + (size_t)(s + 2) * 128,
                         sw0, rstride);
        CP_COMMIT();

        uint32_t saA = sb + (uint32_t)(s % 3) * GM_SLOTSZ;
        uint32_t saB = saA + 16384;

        #pragma unroll
        for (int ks = 0; ks < 4; ks++) {
            uint32_t xo = (uint32_t)(ks << 5);
            uint32_t a[4][4], b[8][2];
            #pragma unroll
            for (int mf = 0; mf < 4; mf++)
                ldsm4(a[mf][0], a[mf][1], a[mf][2], a[mf][3], saA + (PA[mf] ^ xo));
            #pragma unroll
            for (int p = 0; p < 4; p++) {
                uint32_t r0_, r1_, r2_, r3_;
                ldsm4(r0_, r1_, r2_, r3_, saB + (PB[p] ^ xo));
                b[2 * p][0] = r0_; b[2 * p][1] = r2_;
                b[2 * p + 1][0] = r1_; b[2 * p + 1][1] = r3_;
            }
            #pragma unroll
            for (int mf = 0; mf < 4; mf++)
                #pragma unroll
                for (int nf = 0; nf < 8; nf++)
                    mma_f16(acc[mf][nf], a[mf], b[nf]);
        }
    }
}

// ------------------------------------------------------------------
// Generic GEMM. EPI: 0=none 1=silu 2=relu^2 3=sigmoid 4=res+gate*acc
// ------------------------------------------------------------------
template<int EPI, bool HOUT>
__global__ void __launch_bounds__(GM_NT, 2) gemm_h(
    const __half* __restrict__ A, const __half* __restrict__ B,
    const float* __restrict__ res, const float* __restrict__ gate,
    void* __restrict__ Cout, int M, int N, int K)
{
    extern __shared__ char smem[];
    uint32_t sb = smem_u32(smem);
    int tid = threadIdx.x;
    int lane = tid & 31, warp = tid >> 5;
    int wm = warp >> 1, wn = warp & 1;
    int bm = blockIdx.y * 128;
    int bn = blockIdx.x * 128;

    float acc[4][8][4];
    #pragma unroll
    for (int i = 0; i < 4; i++)
        #pragma unroll
        for (int j = 0; j < 8; j++)
            #pragma unroll
            for (int l = 0; l < 4; l++) acc[i][j][l] = 0.f;

    gemm_core(A + (size_t)bm * K, B + (size_t)bn * K, K, sb, tid, lane, wm, wn, acc);

    int r0r = bm + wm * 64 + (lane >> 2);
    int cbase = bn + wn * 64 + (lane & 3) * 2;
    #pragma unroll
    for (int mf = 0; mf < 4; mf++) {
        #pragma unroll
        for (int half = 0; half < 2; half++) {
            int m = r0r + mf * 16 + half * 8;
            size_t rowoff = (size_t)m * N + cbase;
            #pragma unroll
            for (int nf = 0; nf < 8; nf++) {
                float vx = acc[mf][nf][half * 2 + 0];
                float vy = acc[mf][nf][half * 2 + 1];
                size_t o = rowoff + nf * 8;
                if (EPI == 4) {
                    float2 rv = *(const float2*)(res + o);
                    float2 gv = *(const float2*)(gate + o);
                    vx = fmaf(gv.x, vx, rv.x); vy = fmaf(gv.y, vy, rv.y);
                } else if (res) {
                    float2 rv = *(const float2*)(res + o);
                    vx += rv.x; vy += rv.y;
                }
                if (EPI == 1) {
                    vx = vx / (1.f + expf(-vx)); vy = vy / (1.f + expf(-vy));
                } else if (EPI == 2) {
                    vx = fmaxf(vx, 0.f); vx *= vx;
                    vy = fmaxf(vy, 0.f); vy *= vy;
                } else if (EPI == 3) {
                    vx = 1.f / (1.f + expf(-vx)); vy = 1.f / (1.f + expf(-vy));
                }
                if (HOUT) {
                    *(uint32_t*)((__half*)Cout + o) = pack2(vx, vy);
                } else {
                    *(float2*)((float*)Cout + o) = make_float2(vx, vy);
                }
            }
        }
    }
}

// ------------------------------------------------------------------
// Batched 4-way projection GEMM (r,k,v fp32; g silu fp16).
// ------------------------------------------------------------------
struct Proj4 {
    const __half* A[4];
    const __half* W[4];
    float* Cf[3];
    __half* Ch;
};

__global__ void __launch_bounds__(GM_NT, 2) gemm_proj4(Proj4 p)
{
    extern __shared__ char smem[];
    uint32_t sb = smem_u32(smem);
    int tid = threadIdx.x;
    int lane = tid & 31, warp = tid >> 5;
    int wm = warp >> 1, wn = warp & 1;
    int bm = blockIdx.y * 128;
    int bn = blockIdx.x * 128;
    int z = blockIdx.z;

    float acc[4][8][4];
    #pragma unroll
    for (int i = 0; i < 4; i++)
        #pragma unroll
        for (int j = 0; j < 8; j++)
            #pragma unroll
            for (int l = 0; l < 4; l++) acc[i][j][l] = 0.f;

    gemm_core(p.A[z] + (size_t)bm * CC, p.W[z] + (size_t)bn * CC, CC,
              sb, tid, lane, wm, wn, acc);

    int r0r = bm + wm * 64 + (lane >> 2);
    int cbase = bn + wn * 64 + (lane & 3) * 2;
    bool is_g = (z == 3);
    #pragma unroll
    for (int mf = 0; mf < 4; mf++) {
        #pragma unroll
        for (int half = 0; half < 2; half++) {
            int m = r0r + mf * 16 + half * 8;
            size_t rowoff = (size_t)m * CC + cbase;
            #pragma unroll
            for (int nf = 0; nf < 8; nf++) {
                float vx = acc[mf][nf][half * 2 + 0];
                float vy = acc[mf][nf][half * 2 + 1];
                size_t o = rowoff + nf * 8;
                if (is_g) {
                    vx = vx / (1.f + expf(-vx));
                    vy = vy / (1.f + expf(-vy));
                    *(uint32_t*)(p.Ch + o) = pack2(vx, vy);
                } else {
                    *(float2*)(p.Cf[z] + o) = make_float2(vx, vy);
                }
            }
        }
    }
}

// ------------------------------------------------------------------
// wkv sweep 1: chunk-local END-STATE only. Padded smem layout:
// slot = 2 steps x (k: 4x20 pad = 80 | v: 64) = 288 floats; ring of 3.
// ------------------------------------------------------------------
__global__ void __launch_bounds__(256) wkv_s1_kernel(
    const float* __restrict__ k, const float* __restrict__ v,
    const float* __restrict__ decay, float* __restrict__ Schunk)
{
    int blk = blockIdx.x;
    int bh = blk >> 4, c = blk & (WKV_NC - 1);
    int b = bh / HH, h = bh % HH;
    int tid = threadIdx.x;
    int j = tid >> 2, ig = tid & 3;

    float S[16], ww[16];
    #pragma unroll
    for (int m = 0; m < 16; m++) {
        S[m] = 0.f;
        ww[m] = expf(-expf(decay[h * NN + ig * 16 + m]));
    }

    __shared__ __align__(16) float buf[3 * 288];
    uint32_t sbuf = smem_u32(buf);

    size_t base = ((size_t)b * TT + (size_t)c * WKV_L) * CC + h * NN;

    const float* srcs[2] = { k, v };
    int lstep = tid >> 5;                 // 0/1 for tid<64
    int lrem = tid & 31;
    int part = lrem >> 4;                 // 0=k, 1=v
    int off4 = (lrem & 15) * 4;
    uint32_t doff = (part == 0) ? padoff(off4) : (80u + (uint32_t)off4);

    #pragma unroll
    for (int pi = 0; pi < 2; pi++) {
        if (tid < 64)
            cp16(sbuf + (uint32_t)(pi * 288 + lstep * 144 + doff) * 4,
                 srcs[part] + base + (size_t)(2 * pi + lstep) * CC + off4);
        CP_COMMIT();
    }

    const int NPAIR = WKV_L / 2;
    for (int pi = 0; pi < NPAIR; pi++) {
        CP_WAIT(1);
        __syncthreads();
        if (pi + 2 < NPAIR && tid < 64)
            cp16(sbuf + (uint32_t)(((pi + 2) % 3) * 288 + lstep * 144 + doff) * 4,
                 srcs[part] + base + (size_t)(2 * (pi + 2) + lstep) * CC + off4);
        CP_COMMIT();

        const float* slot = buf + (pi % 3) * 288;
        #pragma unroll
        for (int s = 0; s < 2; s++) {
            const float* sl = slot + s * 144;
            float4 K4[4];
            #pragma unroll
            for (int q = 0; q < 4; q++)
                K4[q] = *(const float4*)(sl + ig * 20 + q * 4);
            float vj = sl[80 + j];
            const float* kk = (const float*)K4;
            #pragma unroll
            for (int m = 0; m < 16; m++)
                S[m] = fmaf(ww[m], S[m], kk[m] * vj);
        }
    }

    size_t sbase = (size_t)blk * 4096 + (size_t)j * 64 + ig * 16;
    #pragma unroll
    for (int q = 0; q < 4; q++)
        *(float4*)(Schunk + sbase + q * 4) =
            make_float4(S[q * 4 + 0], S[q * 4 + 1], S[q * 4 + 2], S[q * 4 + 3]);
}

// ------------------------------------------------------------------
// wkv scan: in-place exclusive scan over chunks.
// ------------------------------------------------------------------
__global__ void __launch_bounds__(256) wkv_scan_kernel(
    const float* __restrict__ decay, float* __restrict__ Schunk)
{
    int idx = blockIdx.x * 256 + threadIdx.x;
    int bh = idx >> 12;
    int e = idx & 4095;
    int h = bh % HH;
    int i = e & 63;
    float ewL = expf(-expf(decay[h * NN + i]) * (float)WKV_L);

    size_t base = (size_t)bh * WKV_NC * 4096 + e;
    float sinit = 0.f;
    #pragma unroll
    for (int c = 0; c < WKV_NC; c++) {
        size_t o = base + (size_t)c * 4096;
        float cur = Schunk[o];
        Schunk[o] = sinit;
        sinit = fmaf(ewL, sinit, cur);
    }
}

// ------------------------------------------------------------------
// wkv sweep 2: full recurrence with init state. Padded layout:
// slot = 2 steps x (r: 80 | k: 80 | v: 64) = 448 floats; ring of 3.
// ------------------------------------------------------------------
__global__ void __launch_bounds__(256) wkv_s2_kernel(
    const float* __restrict__ r, const float* __restrict__ k,
    const float* __restrict__ v,
    const float* __restrict__ decay, const float* __restrict__ faaaa,
    const float* __restrict__ Schunk, float* __restrict__ out)
{
    int blk = blockIdx.x;
    int bh = blk >> 4, c = blk & (WKV_NC - 1);
    int b = bh / HH, h = bh % HH;
    int tid = threadIdx.x;
    int j = tid >> 2, ig = tid & 3;

    float S[16], uu[16], ww[16];
    size_t sbase = (size_t)blk * 4096 + (size_t)j * 64 + ig * 16;
    #pragma unroll
    for (int q = 0; q < 4; q++) {
        float4 sv = *(const float4*)(Schunk + sbase + q * 4);
        S[q * 4 + 0] = sv.x; S[q * 4 + 1] = sv.y;
        S[q * 4 + 2] = sv.z; S[q * 4 + 3] = sv.w;
    }
    #pragma unroll
    for (int m = 0; m < 16; m++) {
        int i = ig * 16 + m;
        uu[m] = faaaa[h * NN + i];
        ww[m] = expf(-expf(decay[h * NN + i]));
    }

    __shared__ __align__(16) float buf[3 * 448];
    uint32_t sbuf = smem_u32(buf);

    size_t base = ((size_t)b * TT + (size_t)c * WKV_L) * CC + h * NN;

    const float* srcs[3] = { r, k, v };
    int lstep = tid / 48;
    int lrem = tid % 48;
    int part = lrem >> 4;
    int off4 = (lrem & 15) * 4;
    uint32_t doff = (part < 2) ? ((uint32_t)part * 80 + padoff(off4))
                               : (160u + (uint32_t)off4);

    #pragma unroll
    for (int pi = 0; pi < 2; pi++) {
        if (tid < 96)
            cp16(sbuf + (uint32_t)(pi * 448 + lstep * 224 + doff) * 4,
                 srcs[part] + base + (size_t)(2 * pi + lstep) * CC + off4);
        CP_COMMIT();
    }

    const int NPAIR = WKV_L / 2;
    for (int pi = 0; pi < NPAIR; pi++) {
        CP_WAIT(1);
        __syncthreads();
        if (pi + 2 < NPAIR && tid < 96)
            cp16(sbuf + (uint32_t)(((pi + 2) % 3) * 448 + lstep * 224 + doff) * 4,
                 srcs[part] + base + (size_t)(2 * (pi + 2) + lstep) * CC + off4);
        CP_COMMIT();

        const float* slot = buf + (pi % 3) * 448;
        #pragma unroll
        for (int s = 0; s < 2; s++) {
            const float* sl = slot + s * 224;
            float4 R4[4], K4[4];
            #pragma unroll
            for (int q = 0; q < 4; q++) {
                R4[q] = *(const float4*)(sl + ig * 20 + q * 4);
                K4[q] = *(const float4*)(sl + 80 + ig * 20 + q * 4);
            }
            float vj = sl[160 + j];
            const float* rr = (const float*)R4;
            const float* kk = (const float*)K4;
            float y = 0.f;
            #pragma unroll
            for (int m = 0; m < 16; m++) {
                float a = kk[m] * vj;
                y = fmaf(rr[m], fmaf(uu[m], a, S[m]), y);
                S[m] = fmaf(ww[m], S[m], a);
            }
            y += __shfl_xor_sync(0xffffffffu, y, 1);
            y += __shfl_xor_sync(0xffffffffu, y, 2);
            if (ig == 0) out[base + (size_t)(2 * pi + s) * CC + j] = y;
        }
    }
}

// ------------------------------------------------------------------
// Batched fp32 -> fp16 conversion for all 8 weights (one launch).
// ------------------------------------------------------------------
struct Cvt8 {
    const float4* src[8];
    uint2* dst[8];
    int n4[8];
};

__global__ void __launch_bounds__(256) cvt8_kernel(Cvt8 c)
{
    int z = blockIdx.z;
    int i = blockIdx.x * 256 + threadIdx.x;
    if (i < c.n4[z]) {
        float4 v = c.src[z][i];
        c.dst[z][i] = make_uint2(pack2(v.x, v.y), pack2(v.z, v.w));
    }
}

// ------------------------------------------------------------------
// Block-wide reduction of (sum, sumsq) across 256 threads
// ------------------------------------------------------------------
__device__ __forceinline__ void block_reduce_2(float& s, float& s2) {
    __shared__ float sh[16];
    #pragma unroll
    for (int o = 16; o > 0; o >>= 1) {
        s  += __shfl_xor_sync(0xffffffffu, s,  o);
        s2 += __shfl_xor_sync(0xffffffffu, s2, o);
    }
    int wid = threadIdx.x >> 5;
    if ((threadIdx.x & 31) == 0) { sh[wid] = s; sh[8 + wid] = s2; }
    __syncthreads();
    float a = 0.f, b = 0.f;
    #pragma unroll
    for (int i = 0; i < 8; i++) { a += sh[i]; b += sh[8 + i]; }
    s = a; s2 = b;
    __syncthreads();
}

__device__ __forceinline__ float4 ln_apply(float4 v, float mu, float rstd,
                                           const float4 w, const float4 b) {
    return make_float4((v.x - mu) * rstd * w.x + b.x,
                       (v.y - mu) * rstd * w.y + b.y,
                       (v.z - mu) * rstd * w.z + b.z,
                       (v.w - mu) * rstd * w.w + b.w);
}
__device__ __forceinline__ void sum2_f4(float4 v, float& s, float& s2) {
    s += v.x + v.y + v.z + v.w;
    s2 += v.x * v.x + v.y * v.y + v.z * v.z + v.w * v.w;
}

// ------------------------------------------------------------------
// Fused ln0+ln1+mix4 (one block per row).
// ------------------------------------------------------------------
__global__ void __launch_bounds__(256) l01m4_kernel(
    const float* __restrict__ x,
    const float* __restrict__ w0, const float* __restrict__ b0,
    const float* __restrict__ w1, const float* __restrict__ b1,
    const float* __restrict__ tmk, const float* __restrict__ tmv,
    const float* __restrict__ tmr, const float* __restrict__ tmg,
    float* __restrict__ x0,
    uint2* __restrict__ xk, uint2* __restrict__ xv,
    uint2* __restrict__ xr, uint2* __restrict__ xg)
{
    int row = blockIdx.x;
    int tseq = row & (TT - 1);
    int c = threadIdx.x * 4;
    size_t base = (size_t)row * CC;
    float4 W0 = *(const float4*)(w0 + c), B0v = *(const float4*)(b0 + c);
    float4 W1 = *(const float4*)(w1 + c), B1v = *(const float4*)(b1 + c);

    float4 ct = *(const float4*)(x + base + c);
    float s = 0.f, s2 = 0.f;
    sum2_f4(ct, s, s2);
    block_reduce_2(s, s2);
    float mu = s * (1.f / CC);
    float rstd = rsqrtf(s2 * (1.f / CC) - mu * mu + EPSV);
    float4 t0 = ln_apply(ct, mu, rstd, W0, B0v);
    *(float4*)(x0 + base + c) = t0;
    s = 0.f; s2 = 0.f;
    sum2_f4(t0, s, s2);
    block_reduce_2(s, s2);
    mu = s * (1.f / CC);
    rstd = rsqrtf(s2 * (1.f / CC) - mu * mu + EPSV);
    float4 nt = ln_apply(t0, mu, rstd, W1, B1v);

    float4 np = make_float4(0.f, 0.f, 0.f, 0.f);
    if (tseq != 0) {
        float4 cp = *(const float4*)(x + base - CC + c);
        s = 0.f; s2 = 0.f;
        sum2_f4(cp, s, s2);
        block_reduce_2(s, s2);
        mu = s * (1.f / CC);
        rstd = rsqrtf(s2 * (1.f / CC) - mu * mu + EPSV);
        float4 p0 = ln_apply(cp, mu, rstd, W0, B0v);
        s = 0.f; s2 = 0.f;
        sum2_f4(p0, s, s2);
        block_reduce_2(s, s2);
        mu = s * (1.f / CC);
        rstd = rsqrtf(s2 * (1.f / CC) - mu * mu + EPSV);
        np = ln_apply(p0, mu, rstd, W1, B1v);
    }

    float dx = nt.x - np.x, dy = nt.y - np.y, dz = nt.z - np.z, dw = nt.w - np.w;
    int o = (int)(base / 4) + threadIdx.x;
    float4 m;
    m = *(const float4*)(tmk + c);
    xk[o] = make_uint2(pack2(fmaf(dx, m.x, np.x), fmaf(dy, m.y, np.y)),
                       pack2(fmaf(dz, m.z, np.z), fmaf(dw, m.w, np.w)));
    m = *(const float4*)(tmv + c);
    xv[o] = make_uint2(pack2(fmaf(dx, m.x, np.x), fmaf(dy, m.y, np.y)),
                       pack2(fmaf(dz, m.z, np.z), fmaf(dw, m.w, np.w)));
    m = *(const float4*)(tmr + c);
    xr[o] = make_uint2(pack2(fmaf(dx, m.x, np.x), fmaf(dy, m.y, np.y)),
                       pack2(fmaf(dz, m.z, np.z), fmaf(dw, m.w, np.w)));
    m = *(const float4*)(tmg + c);
    xg[o] = make_uint2(pack2(fmaf(dx, m.x, np.x), fmaf(dy, m.y, np.y)),
                       pack2(fmaf(dz, m.z, np.z), fmaf(dw, m.w, np.w)));
}

// ------------------------------------------------------------------
// Fused ln2+mix2 (one block per row).
// ------------------------------------------------------------------
__global__ void __launch_bounds__(256) lnm2_kernel(
    const float* __restrict__ in,
    const float* __restrict__ w, const float* __restrict__ b,
    const float* __restrict__ tmk, const float* __restrict__ tmr,
    uint2* __restrict__ xk, uint2* __restrict__ xr)
{
    int row = blockIdx.x;
    int tseq = row & (TT - 1);
    int c = threadIdx.x * 4;
    size_t base = (size_t)row * CC;
    float4 W = *(const float4*)(w + c), Bv = *(const float4*)(b + c);

    float4 ct = *(const float4*)(in + base + c);
    float s = 0.f, s2 = 0.f;
    sum2_f4(ct, s, s2);
    block_reduce_2(s, s2);
    float mu = s * (1.f / CC);
    float rstd = rsqrtf(s2 * (1.f / CC) - mu * mu + EPSV);
    float4 nt = ln_apply(ct, mu, rstd, W, Bv);

    float4 np = make_float4(0.f, 0.f, 0.f, 0.f);
    if (tseq != 0) {
        float4 cp = *(const float4*)(in + base - CC + c);
        s = 0.f; s2 = 0.f;
        sum2_f4(cp, s, s2);
        block_reduce_2(s, s2);
        mu = s * (1.f / CC);
        rstd = rsqrtf(s2 * (1.f / CC) - mu * mu + EPSV);
        np = ln_apply(cp, mu, rstd, W, Bv);
    }

    float dx = nt.x - np.x, dy = nt.y - np.y, dz = nt.z - np.z, dw = nt.w - np.w;
    int o = (int)(base / 4) + threadIdx.x;
    float4 m;
    m = *(const float4*)(tmk + c);
    xk[o] = make_uint2(pack2(fmaf(dx, m.x, np.x), fmaf(dy, m.y, np.y)),
                       pack2(fmaf(dz, m.z, np.z), fmaf(dw, m.w, np.w)));
    m = *(const float4*)(tmr + c);
    xr[o] = make_uint2(pack2(fmaf(dx, m.x, np.x), fmaf(dy, m.y, np.y)),
                       pack2(fmaf(dz, m.z, np.z), fmaf(dw, m.w, np.w)));
}

// ------------------------------------------------------------------
// GroupNorm(y/8) * g(fp16) -> fp16 (vectorized: thread t = 4 channels)
// 16 threads per 64-channel group; groups aligned within warps.
// ------------------------------------------------------------------
__global__ void __launch_bounds__(256) gn_gate_kernel(
    const float* __restrict__ y, const __half* __restrict__ g,
    const float* __restrict__ w, const float* __restrict__ b,
    __half* __restrict__ out)
{
    int row = blockIdx.x;
    size_t base = (size_t)row * CC;
    int gi = threadIdx.x >> 4;           // group 0..15
    int sub = threadIdx.x & 15;          // position in group
    int c = gi * 64 + sub * 4;

    float4 v = *(const float4*)(y + base + c);
    v.x *= 0.125f; v.y *= 0.125f; v.z *= 0.125f; v.w *= 0.125f;
    float s = v.x + v.y + v.z + v.w;
    float s2 = v.x * v.x + v.y * v.y + v.z * v.z + v.w * v.w;
    #pragma unroll
    for (int o = 8; o > 0; o >>= 1) {
        s  += __shfl_xor_sync(0xffffffffu, s,  o);
        s2 += __shfl_xor_sync(0xffffffffu, s2, o);
    }
    float mu = s * (1.f / 64);
    float rstd = rsqrtf(s2 * (1.f / 64) - mu * mu + EPSV);

    float4 W = *(const float4*)(w + c);
    float4 Bv = *(const float4*)(b + c);
    uint2 gp = *(const uint2*)(g + base + c);
    __half2 g01 = *(__half2*)&gp.x;
    __half2 g23 = *(__half2*)&gp.y;
    float2 gf01 = __half22float2(g01);
    float2 gf23 = __half22float2(g23);

    float o0 = ((v.x - mu) * rstd * W.x + Bv.x) * gf01.x;
    float o1 = ((v.y - mu) * rstd * W.y + Bv.y) * gf01.y;
    float o2 = ((v.z - mu) * rstd * W.z + Bv.z) * gf23.x;
    float o3 = ((v.w - mu) * rstd * W.w + Bv.w) * gf23.y;
    *(uint2*)(out + base + c) = make_uint2(pack2(o0, o1), pack2(o2, o3));
}

// ------------------------------------------------------------------
// Launch
// ------------------------------------------------------------------
extern "C" void kernel_launch(void* const* d_in, const int* in_sizes, int n_in,
                              void* d_out, int out_size)
{
    const float* x        = (const float*)d_in[0];
    const float* ln0_w    = (const float*)d_in[1];
    const float* ln0_b    = (const float*)d_in[2];
    const float* ln1_w    = (const float*)d_in[3];
    const float* ln1_b    = (const float*)d_in[4];
    const float* ln2_w    = (const float*)d_in[5];
    const float* ln2_b    = (const float*)d_in[6];
    const float* att_tmk  = (const float*)d_in[7];
    const float* att_tmv  = (const float*)d_in[8];
    const float* att_tmr  = (const float*)d_in[9];
    const float* att_tmg  = (const float*)d_in[10];
    const float* att_decay= (const float*)d_in[11];
    const float* att_faaaa= (const float*)d_in[12];
    const float* att_Wr   = (const float*)d_in[13];
    const float* att_Wk   = (const float*)d_in[14];
    const float* att_Wv   = (const float*)d_in[15];
    const float* att_Wg   = (const float*)d_in[16];
    const float* att_Wo   = (const float*)d_in[17];
    const float* lnx_w    = (const float*)d_in[18];
    const float* lnx_b    = (const float*)d_in[19];
    const float* ffn_tmk  = (const float*)d_in[20];
    const float* ffn_tmr  = (const float*)d_in[21];
    const float* ffn_Wk   = (const float*)d_in[22];
    const float* ffn_Wr   = (const float*)d_in[23];
    const float* ffn_Wv   = (const float*)d_in[24];

    float* base = nullptr;
    cudaGetSymbolAddress((void**)&base, g_bufs);
    __half* H = nullptr;
    cudaGetSymbolAddress((void**)&H, g_h);
    __half* FH = nullptr;
    cudaGetSymbolAddress((void**)&FH, g_fh);
    __half* WH = nullptr;
    cudaGetSymbolAddress((void**)&WH, g_wh);

    float* B0 = base + 0 * (size_t)BT * CC;
    float* B1 = base + 1 * (size_t)BT * CC;
    float* B2 = base + 2 * (size_t)BT * CC;   // Schunk scratch
    float* B3 = base + 3 * (size_t)BT * CC;
    float* B5 = base + 5 * (size_t)BT * CC;
    float* B6 = base + 6 * (size_t)BT * CC;
    float* B7 = base + 7 * (size_t)BT * CC;
    __half* H0 = H + 0 * (size_t)BT * CC;
    __half* H1 = H + 1 * (size_t)BT * CC;
    __half* H2 = H + 2 * (size_t)BT * CC;
    __half* H3 = H + 3 * (size_t)BT * CC;
    __half* WHr = WH + 0 * CCSQ;
    __half* WHk = WH + 1 * CCSQ;
    __half* WHv = WH + 2 * CCSQ;
    __half* WHg = WH + 3 * CCSQ;
    __half* WHo = WH + 4 * CCSQ;
    __half* WHfr = WH + 5 * CCSQ;
    __half* WHfk = WH + 6 * CCSQ;
    __half* WHfv = WHfk + (size_t)FFND * CC;
    float* out = (float*)d_out;
    float* Schunk = B2;

    cudaFuncSetAttribute(gemm_h<0,false>, cudaFuncAttributeMaxDynamicSharedMemorySize, GM_SMEM);
    cudaFuncSetAttribute(gemm_h<2,true>,  cudaFuncAttributeMaxDynamicSharedMemorySize, GM_SMEM);
    cudaFuncSetAttribute(gemm_h<3,false>, cudaFuncAttributeMaxDynamicSharedMemorySize, GM_SMEM);
    cudaFuncSetAttribute(gemm_h<4,false>, cudaFuncAttributeMaxDynamicSharedMemorySize, GM_SMEM);
    cudaFuncSetAttribute(gemm_proj4,      cudaFuncAttributeMaxDynamicSharedMemorySize, GM_SMEM);

    dim3 gC(CC / 128, BT / 128);
    dim3 gP(CC / 128, BT / 128, 4);
    dim3 gF(FFND / 128, BT / 128);

    // batched weight conversion
    {
        Cvt8 c;
        c.src[0] = (const float4*)att_Wr; c.dst[0] = (uint2*)WHr; c.n4[0] = CCSQ / 4;
        c.src[1] = (const float4*)att_Wk; c.dst[1] = (uint2*)WHk; c.n4[1] = CCSQ / 4;
        c.src[2] = (const float4*)att_Wv; c.dst[2] = (uint2*)WHv; c.n4[2] = CCSQ / 4;
        c.src[3] = (const float4*)att_Wg; c.dst[3] = (uint2*)WHg; c.n4[3] = CCSQ / 4;
        c.src[4] = (const float4*)att_Wo; c.dst[4] = (uint2*)WHo; c.n4[4] = CCSQ / 4;
        c.src[5] = (const float4*)ffn_Wr; c.dst[5] = (uint2*)WHfr; c.n4[5] = CCSQ / 4;
        c.src[6] = (const float4*)ffn_Wk; c.dst[6] = (uint2*)WHfk; c.n4[6] = (int)((size_t)FFND * CC / 4);
        c.src[7] = (const float4*)ffn_Wv; c.dst[7] = (uint2*)WHfv; c.n4[7] = (int)((size_t)FFND * CC / 4);
        dim3 gcv((unsigned)(((size_t)FFND * CC / 4 + 255) / 256), 1, 8);
        cvt8_kernel<<<gcv, 256>>>(c);
    }

    // fused ln0+ln1+mix4
    l01m4_kernel<<<BT, 256>>>(x, ln0_w, ln0_b, ln1_w, ln1_b,
                              att_tmk, att_tmv, att_tmr, att_tmg,
                              B0, (uint2*)H0, (uint2*)H1, (uint2*)H2, (uint2*)H3);
    // batched projections: r->B6, k->B7, v->B1, g(silu,fp16)->FH
    {
        Proj4 p;
        p.A[0] = H2; p.W[0] = WHr; p.Cf[0] = B6;
        p.A[1] = H0; p.W[1] = WHk; p.Cf[1] = B7;
        p.A[2] = H1; p.W[2] = WHv; p.Cf[2] = B1;
        p.A[3] = H3; p.W[3] = WHg; p.Ch = FH;
        gemm_proj4<<<gP, GM_NT, GM_SMEM>>>(p);
    }
    // chunked wkv: state sweep -> scan -> full sweep
    wkv_s1_kernel<<<BQ * HH * WKV_NC, 256>>>(B7, B1, att_decay, Schunk);
    wkv_scan_kernel<<<(BQ * HH * 4096) / 256, 256>>>(att_decay, Schunk);
    wkv_s2_kernel<<<BQ * HH * WKV_NC, 256>>>(B6, B7, B1, att_decay, att_faaaa,
                                             Schunk, B3);
    // groupnorm(y/8) * g -> H0 (fp16)
    gn_gate_kernel<<<BT, 256>>>(B3, FH, lnx_w, lnx_b, H0);
    // x_att = x0 + (gy) @ Wo^T -> B5
    gemm_h<0,false><<<gC, GM_NT, GM_SMEM>>>(H0, WHo, B0, nullptr, B5, BT, CC, CC);
    // fused ln2+mix2: B5 -> H2=xk, H3=xr (fp16)
    lnm2_kernel<<<BT, 256>>>(B5, ln2_w, ln2_b, ffn_tmk, ffn_tmr,
                             (uint2*)H2, (uint2*)H3);
    gemm_h<2,true><<<gF, GM_NT, GM_SMEM>>>(H2, WHfk, nullptr, nullptr, FH, BT, FFND, CC);
    gemm_h<3,false><<<gC, GM_NT, GM_SMEM>>>(H3, WHfr, nullptr, nullptr, B7, BT, CC, CC);
    gemm_h<4,false><<<gC, GM_NT, GM_SMEM>>>(FH, WHfv, B5, B7, out, BT, CC, FFND);
}